// round 10
// baseline (speedup 1.0000x reference)
#include <cuda_runtime.h>
#include <cuda_bf16.h>
#include <cuda_fp16.h>
#include <math.h>

#define NN 50000
#define EE 640000
#define F  128
#define NB ((NN + 1023) / 1024)          // 49 scan blocks
#define GB ((NN + 127) / 128)            // 391 gemm blocks

// ---- smem layout (bytes). Rows padded to 272B (136 bf16) -> ldmatrix conflict-free
#define ROWB 272
#define AH_OFF 0
#define AL_OFF 34816
#define BH_OFF 69632
#define BL_OFF 104448
#define S1_OFF 139264
#define S2_OFF 139776
#define SMEM_BYTES 140288

// Scratch (static device globals: no allocation anywhere)
__device__ float  g_h[NN * F];
__device__ __half g_hh[NN * F];      // fp16 copy of h for the gather
__device__ float  g_s1[NN];
__device__ float  g_s2[NN];
__device__ int    g_count[NN];
__device__ int    g_rowstart[NN];
__device__ int    g_rank[EE];
__device__ int    g_agg[64];
__device__ int    g_done;
__device__ int2   g_pair[EE];
__device__ unsigned g_Bimg[16384];   // [BH: 8192 u32][BL: 8192 u32], [n][k] bf16 pairs

// ------------------------------------------------ PTX helpers (baseline ISA only)
__device__ __forceinline__ unsigned smem_u32(const void* p) {
    unsigned a;
    asm("{ .reg .u64 t; cvta.to.shared.u64 t, %1; cvt.u32.u64 %0, t; }"
        : "=r"(a) : "l"(p));
    return a;
}
__device__ __forceinline__ void ldm4(unsigned r[4], unsigned addr) {
    asm volatile("ldmatrix.sync.aligned.m8n8.x4.shared.b16 {%0,%1,%2,%3}, [%4];"
                 : "=r"(r[0]), "=r"(r[1]), "=r"(r[2]), "=r"(r[3]) : "r"(addr));
}
__device__ __forceinline__ void mma16816(float c[4], const unsigned a[4],
                                         unsigned b0, unsigned b1) {
    asm volatile("mma.sync.aligned.m16n8k16.row.col.f32.bf16.bf16.f32 "
                 "{%0,%1,%2,%3}, {%4,%5,%6,%7}, {%8,%9}, {%0,%1,%2,%3};"
                 : "+f"(c[0]), "+f"(c[1]), "+f"(c[2]), "+f"(c[3])
                 : "r"(a[0]), "r"(a[1]), "r"(a[2]), "r"(a[3]), "r"(b0), "r"(b1));
}
__device__ __forceinline__ unsigned pack_bf16(float x, float y) {
    unsigned short hx = __bfloat16_as_ushort(__float2bfloat16(x));
    unsigned short hy = __bfloat16_as_ushort(__float2bfloat16(y));
    return (unsigned)hx | ((unsigned)hy << 16);
}
__device__ __forceinline__ float bf16hi_f(float x) {   // value of bf16(x)
    unsigned short h = __bfloat16_as_ushort(__float2bfloat16(x));
    return __uint_as_float(((unsigned)h) << 16);
}

// -------------------- prep: init counters + W -> bf16 hi/lo images [n][k]
__global__ void k_prep(const float* __restrict__ W) {
    int t = blockIdx.x * blockDim.x + threadIdx.x;
    if (t < NN) g_count[t] = 0;
    if (t < 64) g_agg[t] = -1;
    if (t == 64) g_done = 0;
    if (t < 8192) {
        int n = t >> 6, q = t & 63, k = 2 * q;
        float v0 = W[(size_t)k * F + n];          // B[n][k] = W[k][n]
        float v1 = W[(size_t)(k + 1) * F + n];
        float h0 = bf16hi_f(v0), h1 = bf16hi_f(v1);
        g_Bimg[n * 64 + q]        = pack_bf16(v0, v1);
        g_Bimg[8192 + n * 64 + q] = pack_bf16(v0 - h0, v1 - h1);
    }
}

// ------------- GEMM via mma.sync bf16-split + s1/s2 epilogue + hist tail
__global__ void __launch_bounds__(256, 1)
k_gemm(const float* __restrict__ x, const float* __restrict__ a,
       const int* __restrict__ src) {
    extern __shared__ char dsm[];
    const unsigned base = smem_u32(dsm);
    float* s_s1 = (float*)(dsm + S1_OFF);
    float* s_s2 = (float*)(dsm + S2_OFF);

    const int tid = threadIdx.x;
    const int lane = tid & 31;
    const int wid = tid >> 5;
    const int warp_m = wid >> 1;          // 0..3 -> rows warp_m*32..+31
    const int warp_n = wid & 1;           // 0..1 -> cols warp_n*64..+63
    const int rowBase = blockIdx.x * 128;

    // ---- phase 1: fill smem ----
    const float4* bimg4 = (const float4*)g_Bimg;
#pragma unroll
    for (int p = 0; p < 16; p++) {
        int i = p * 256 + tid;            // 4096 float4 (BH 2048 + BL 2048)
        int half_ = i >> 11, j = i & 2047;
        int n = j >> 4, f4 = j & 15;
        *(float4*)(dsm + (half_ ? BL_OFF : BH_OFF) + n * ROWB + f4 * 16) = bimg4[i];
    }
#pragma unroll
    for (int p = 0; p < 16; p++) {
        int idx = p * 256 + tid;          // 4096 float4 slots (128 rows x 32)
        int row = idx >> 5;
        int col0 = (idx & 31) * 4;
        int grow = rowBase + row;
        float4 v = make_float4(0.f, 0.f, 0.f, 0.f);
        if (grow < NN) v = *(const float4*)&x[(size_t)grow * F + col0];
        unsigned h01 = pack_bf16(v.x, v.y);
        unsigned h23 = pack_bf16(v.z, v.w);
        unsigned l01 = pack_bf16(v.x - bf16hi_f(v.x), v.y - bf16hi_f(v.y));
        unsigned l23 = pack_bf16(v.z - bf16hi_f(v.z), v.w - bf16hi_f(v.w));
        unsigned o = row * ROWB + col0 * 2;
        asm volatile("st.shared.v2.b32 [%0], {%1, %2};"
                     :: "r"(base + AH_OFF + o), "r"(h01), "r"(h23));
        asm volatile("st.shared.v2.b32 [%0], {%1, %2};"
                     :: "r"(base + AL_OFF + o), "r"(l01), "r"(l23));
    }
    if (tid < 128) { s_s1[tid] = 0.f; s_s2[tid] = 0.f; }
    __syncthreads();

    // ---- phase 2: mainloop ----
    float acc[2][8][4];
#pragma unroll
    for (int mi = 0; mi < 2; mi++)
#pragma unroll
        for (int ni = 0; ni < 8; ni++)
#pragma unroll
            for (int q = 0; q < 4; q++) acc[mi][ni][q] = 0.f;

    const int lrA = (lane & 7) + ((lane >> 3) & 1) * 8;
    const int kbA = (lane >> 4) * 16;
    const int lrB = (lane & 7) + (lane >> 4) * 8;
    const int kbB = ((lane >> 3) & 1) * 16;

    const unsigned aRowA = base + (warp_m * 32 + lrA) * ROWB + kbA;
    const unsigned aRowB = base + (warp_n * 64 + lrB) * ROWB + kbB;

    for (int k = 0; k < 8; k++) {
        const int kb = k * 32;
        unsigned ah[2][4], al[2][4], bh[4][4], bl[4][4];
#pragma unroll
        for (int mi = 0; mi < 2; mi++) {
            ldm4(ah[mi], aRowA + AH_OFF + mi * 16 * ROWB + kb);
            ldm4(al[mi], aRowA + AL_OFF + mi * 16 * ROWB + kb);
        }
#pragma unroll
        for (int j = 0; j < 4; j++) {
            ldm4(bh[j], aRowB + BH_OFF + j * 16 * ROWB + kb);
            ldm4(bl[j], aRowB + BL_OFF + j * 16 * ROWB + kb);
        }
#pragma unroll
        for (int mi = 0; mi < 2; mi++)
#pragma unroll
            for (int j = 0; j < 4; j++) {
                mma16816(acc[mi][2 * j],     ah[mi], bh[j][0], bh[j][1]);
                mma16816(acc[mi][2 * j + 1], ah[mi], bh[j][2], bh[j][3]);
                mma16816(acc[mi][2 * j],     ah[mi], bl[j][0], bl[j][1]);
                mma16816(acc[mi][2 * j + 1], ah[mi], bl[j][2], bl[j][3]);
                mma16816(acc[mi][2 * j],     al[mi], bh[j][0], bh[j][1]);
                mma16816(acc[mi][2 * j + 1], al[mi], bh[j][2], bh[j][3]);
            }
    }

    // ---- phase 3: epilogue — write h (fp32 + fp16 copy), fused s1/s2 ----
    float p1[2][2] = {{0.f, 0.f}, {0.f, 0.f}};
    float p2[2][2] = {{0.f, 0.f}, {0.f, 0.f}};
#pragma unroll
    for (int ni = 0; ni < 8; ni++) {
        int c = warp_n * 64 + ni * 8 + 2 * (lane & 3);
        float A1x = a[c], A1y = a[c + 1];
        float A2x = a[F + c], A2y = a[F + c + 1];
#pragma unroll
        for (int mi = 0; mi < 2; mi++) {
            float* f = acc[mi][ni];
            p1[mi][0] += f[0] * A1x + f[1] * A1y;
            p2[mi][0] += f[0] * A2x + f[1] * A2y;
            p1[mi][1] += f[2] * A1x + f[3] * A1y;
            p2[mi][1] += f[2] * A2x + f[3] * A2y;
            int row0 = rowBase + warp_m * 32 + mi * 16 + (lane >> 2);
            if (row0 < NN) {
                *(float2*)&g_h[(size_t)row0 * F + c] = make_float2(f[0], f[1]);
                *(__half2*)&g_hh[(size_t)row0 * F + c] = __floats2half2_rn(f[0], f[1]);
            }
            if (row0 + 8 < NN) {
                *(float2*)&g_h[(size_t)(row0 + 8) * F + c] = make_float2(f[2], f[3]);
                *(__half2*)&g_hh[(size_t)(row0 + 8) * F + c] = __floats2half2_rn(f[2], f[3]);
            }
        }
    }
#pragma unroll
    for (int mi = 0; mi < 2; mi++)
#pragma unroll
        for (int hf = 0; hf < 2; hf++) {
            float v1 = p1[mi][hf], v2 = p2[mi][hf];
            v1 += __shfl_xor_sync(0xffffffffu, v1, 1);
            v1 += __shfl_xor_sync(0xffffffffu, v1, 2);
            v2 += __shfl_xor_sync(0xffffffffu, v2, 1);
            v2 += __shfl_xor_sync(0xffffffffu, v2, 2);
            if ((lane & 3) == 0) {
                int lr = warp_m * 32 + mi * 16 + hf * 8 + (lane >> 2);
                atomicAdd(&s_s1[lr], v1);
                atomicAdd(&s_s2[lr], v2);
            }
        }
    __syncthreads();
    if (tid < 128) {
        int row = rowBase + tid;
        if (row < NN) { g_s1[row] = s_s1[tid]; g_s2[row] = s_s2[tid]; }
    }

    // ---- phase 4: histogram tail (independent work) ----
    for (int e = blockIdx.x * 256 + tid; e < EE; e += GB * 256)
        g_rank[e] = atomicAdd(&g_count[src[e]], 1);
}

// ------- fused: exclusive scan (decoupled aggregates) + grid sync + permute
// NB=49 blocks <= 148 SMs -> co-resident, polling is deadlock-free.
__global__ void k_scanperm(const int* __restrict__ src, const int* __restrict__ dst) {
    __shared__ int warpsums[32];
    __shared__ int s_prev;
    const int b = blockIdx.x;
    const int i = b * 1024 + threadIdx.x;
    const int lane = threadIdx.x & 31, w = threadIdx.x >> 5;

    // ---- scan phase ----
    int v = (i < NN) ? g_count[i] : 0;
    int sc = v;
#pragma unroll
    for (int off = 1; off < 32; off <<= 1) {
        int n = __shfl_up_sync(0xffffffffu, sc, off);
        if (lane >= off) sc += n;
    }
    if (lane == 31) warpsums[w] = sc;
    if (threadIdx.x == 0) s_prev = 0;
    __syncthreads();
    if (w == 0) {
        int ws = warpsums[lane];
#pragma unroll
        for (int off = 1; off < 32; off <<= 1) {
            int n = __shfl_up_sync(0xffffffffu, ws, off);
            if (lane >= off) ws += n;
        }
        warpsums[lane] = ws;
    }
    __syncthreads();

    if (threadIdx.x == 0) atomicExch(&g_agg[b], warpsums[31]);
    if (threadIdx.x < b) {
        volatile int* p = &g_agg[threadIdx.x];
        int ag;
        do { ag = *p; } while (ag < 0);
        atomicAdd(&s_prev, ag);
    }
    __syncthreads();

    int basew = (w > 0) ? warpsums[w - 1] : 0;
    if (i < NN) g_rowstart[i] = (sc + basew - v) + s_prev;

    // ---- device-wide sync (co-resident blocks) ----
    __syncthreads();
    if (threadIdx.x == 0) {
        __threadfence();
        atomicAdd(&g_done, 1);
        volatile int* dp = &g_done;
        while (*dp < NB) { }
    }
    __syncthreads();

    // ---- permute phase: ~13 independent edges per thread (deep MLP) ----
    for (int e = b * 1024 + threadIdx.x; e < EE; e += NB * 1024) {
        int s = __ldg(&src[e]);
        int d = __ldg(&dst[e]);
        float scv = g_s1[s] + g_s2[d];
        float lr = fmaxf(scv, 0.2f * scv);         // leaky_relu
        float ev = expf(-lr);
        int pos = __ldcg(&g_rowstart[s]) + g_rank[e];
        g_pair[pos] = make_int2(d, __float_as_int(ev));
    }
}

// ------------------------------------------- gather + finalize (fused)
// One warp per node; pairs fetched coalesced once per 32 edges, shfl-distributed.
__global__ void k_gather(float* __restrict__ out) {
    int node = blockIdx.x * 8 + (threadIdx.x >> 5);
    if (node >= NN) return;
    int lane = threadIdx.x & 31;
    int start = g_rowstart[node];
    int len = g_count[node];

    float4 acc = make_float4(0.f, 0.f, 0.f, 0.f);
    float rowsum = 0.0f;
    const size_t loff = (size_t)lane * 4;

    for (int cbase = 0; cbase < len; cbase += 32) {
        int cnt = min(32, len - cbase);
        int2 myp = (lane < cnt) ? g_pair[start + cbase + lane] : make_int2(0, 0);
        int j = 0;
        for (; j + 1 < cnt; j += 2) {
            int d0 = __shfl_sync(0xffffffffu, myp.x, j);
            float ev0 = __int_as_float(__shfl_sync(0xffffffffu, myp.y, j));
            int d1 = __shfl_sync(0xffffffffu, myp.x, j + 1);
            float ev1 = __int_as_float(__shfl_sync(0xffffffffu, myp.y, j + 1));
            uint2 q0 = *(const uint2*)(g_hh + (size_t)d0 * F + loff);
            uint2 q1 = *(const uint2*)(g_hh + (size_t)d1 * F + loff);
            float2 f00 = __half22float2(*(__half2*)&q0.x);
            float2 f01 = __half22float2(*(__half2*)&q0.y);
            float2 f10 = __half22float2(*(__half2*)&q1.x);
            float2 f11 = __half22float2(*(__half2*)&q1.y);
            rowsum += ev0 + ev1;
            acc.x += ev0 * f00.x + ev1 * f10.x;
            acc.y += ev0 * f00.y + ev1 * f10.y;
            acc.z += ev0 * f01.x + ev1 * f11.x;
            acc.w += ev0 * f01.y + ev1 * f11.y;
        }
        if (j < cnt) {
            int d0 = __shfl_sync(0xffffffffu, myp.x, j);
            float ev0 = __int_as_float(__shfl_sync(0xffffffffu, myp.y, j));
            uint2 q0 = *(const uint2*)(g_hh + (size_t)d0 * F + loff);
            float2 f00 = __half22float2(*(__half2*)&q0.x);
            float2 f01 = __half22float2(*(__half2*)&q0.y);
            rowsum += ev0;
            acc.x += ev0 * f00.x; acc.y += ev0 * f00.y;
            acc.z += ev0 * f01.x; acc.w += ev0 * f01.y;
        }
    }

    float inv = 1.0f / (rowsum + 1e-16f);
    float4 h4 = *(const float4*)(g_h + (size_t)node * F + loff);
    float4 r;
    float v;
    v = h4.x - acc.x * inv; r.x = (v > 0.f) ? v : expm1f(v);
    v = h4.y - acc.y * inv; r.y = (v > 0.f) ? v : expm1f(v);
    v = h4.z - acc.z * inv; r.z = (v > 0.f) ? v : expm1f(v);
    v = h4.w - acc.w * inv; r.w = (v > 0.f) ? v : expm1f(v);
    *(float4*)(out + (size_t)node * F + loff) = r;
}

// ---------------------------------------------------------------- launch
extern "C" void kernel_launch(void* const* d_in, const int* in_sizes, int n_in,
                              void* d_out, int out_size) {
    const float* x = (const float*)d_in[0];
    const float* W = (const float*)d_in[1];
    const float* a = (const float*)d_in[2];
    const int*   ei = (const int*)d_in[3];
    const int* src = ei;
    const int* dst = ei + EE;
    float* out = (float*)d_out;

    cudaFuncSetAttribute(k_gemm, cudaFuncAttributeMaxDynamicSharedMemorySize,
                         SMEM_BYTES);

    k_prep    <<<(NN + 255) / 256, 256>>>(W);
    k_gemm    <<<GB, 256, SMEM_BYTES>>>(x, a, src);
    k_scanperm<<<NB, 1024>>>(src, dst);
    k_gather  <<<(NN + 7) / 8, 256>>>(out);
}

// round 11
// speedup vs baseline: 1.1364x; 1.1364x over previous
#include <cuda_runtime.h>
#include <cuda_bf16.h>
#include <cuda_fp16.h>
#include <math.h>

#define NN 50000
#define EE 640000
#define F  128
#define NB ((NN + 1023) / 1024)          // 49 scan blocks
#define GB ((NN + 127) / 128)            // 391 gemm blocks
#define PT 64000                          // permute threads (EE/PT = 10 exact)

// ---- smem layout (bytes). Rows padded to 272B (136 bf16) -> ldmatrix conflict-free
#define ROWB 272
#define AH_OFF 0
#define AL_OFF 34816
#define BH_OFF 69632
#define BL_OFF 104448
#define S1_OFF 139264
#define S2_OFF 139776
#define SMEM_BYTES 140288

// Scratch (static device globals: no allocation anywhere)
__device__ float  g_h[NN * F];
__device__ __half g_hh[NN * F];      // fp16 copy of h for the gather
__device__ float  g_s1[NN];
__device__ float  g_s2[NN];
__device__ int    g_count[NN];
__device__ int    g_rowstart[NN];
__device__ int    g_rank[EE];
__device__ int    g_agg[64];
__device__ int2   g_pair[EE];
__device__ unsigned g_Bimg[16384];   // [BH: 8192 u32][BL: 8192 u32], [n][k] bf16 pairs

// ------------------------------------------------ PTX helpers (baseline ISA only)
__device__ __forceinline__ unsigned smem_u32(const void* p) {
    unsigned a;
    asm("{ .reg .u64 t; cvta.to.shared.u64 t, %1; cvt.u32.u64 %0, t; }"
        : "=r"(a) : "l"(p));
    return a;
}
__device__ __forceinline__ void ldm4(unsigned r[4], unsigned addr) {
    asm volatile("ldmatrix.sync.aligned.m8n8.x4.shared.b16 {%0,%1,%2,%3}, [%4];"
                 : "=r"(r[0]), "=r"(r[1]), "=r"(r[2]), "=r"(r[3]) : "r"(addr));
}
__device__ __forceinline__ void mma16816(float c[4], const unsigned a[4],
                                         unsigned b0, unsigned b1) {
    asm volatile("mma.sync.aligned.m16n8k16.row.col.f32.bf16.bf16.f32 "
                 "{%0,%1,%2,%3}, {%4,%5,%6,%7}, {%8,%9}, {%0,%1,%2,%3};"
                 : "+f"(c[0]), "+f"(c[1]), "+f"(c[2]), "+f"(c[3])
                 : "r"(a[0]), "r"(a[1]), "r"(a[2]), "r"(a[3]), "r"(b0), "r"(b1));
}
__device__ __forceinline__ unsigned pack_bf16(float x, float y) {
    unsigned short hx = __bfloat16_as_ushort(__float2bfloat16(x));
    unsigned short hy = __bfloat16_as_ushort(__float2bfloat16(y));
    return (unsigned)hx | ((unsigned)hy << 16);
}
__device__ __forceinline__ float bf16hi_f(float x) {   // value of bf16(x)
    unsigned short h = __bfloat16_as_ushort(__float2bfloat16(x));
    return __uint_as_float(((unsigned)h) << 16);
}

// -------------------- prep: init counters + W -> bf16 hi/lo images [n][k]
__global__ void k_prep(const float* __restrict__ W) {
    int t = blockIdx.x * blockDim.x + threadIdx.x;
    if (t < NN) g_count[t] = 0;
    if (t < 64) g_agg[t] = -1;
    if (t < 8192) {
        int n = t >> 6, q = t & 63, k = 2 * q;
        float v0 = W[(size_t)k * F + n];          // B[n][k] = W[k][n]
        float v1 = W[(size_t)(k + 1) * F + n];
        float h0 = bf16hi_f(v0), h1 = bf16hi_f(v1);
        g_Bimg[n * 64 + q]        = pack_bf16(v0, v1);
        g_Bimg[8192 + n * 64 + q] = pack_bf16(v0 - h0, v1 - h1);
    }
}

// ------------- GEMM via mma.sync bf16-split + s1/s2 epilogue + hist tail
__global__ void __launch_bounds__(256, 1)
k_gemm(const float* __restrict__ x, const float* __restrict__ a,
       const int* __restrict__ src) {
    extern __shared__ char dsm[];
    const unsigned base = smem_u32(dsm);
    float* s_s1 = (float*)(dsm + S1_OFF);
    float* s_s2 = (float*)(dsm + S2_OFF);

    const int tid = threadIdx.x;
    const int lane = tid & 31;
    const int wid = tid >> 5;
    const int warp_m = wid >> 1;
    const int warp_n = wid & 1;
    const int rowBase = blockIdx.x * 128;

    // ---- phase 1: fill smem ----
    const float4* bimg4 = (const float4*)g_Bimg;
#pragma unroll
    for (int p = 0; p < 16; p++) {
        int i = p * 256 + tid;
        int half_ = i >> 11, j = i & 2047;
        int n = j >> 4, f4 = j & 15;
        *(float4*)(dsm + (half_ ? BL_OFF : BH_OFF) + n * ROWB + f4 * 16) = bimg4[i];
    }
#pragma unroll
    for (int p = 0; p < 16; p++) {
        int idx = p * 256 + tid;
        int row = idx >> 5;
        int col0 = (idx & 31) * 4;
        int grow = rowBase + row;
        float4 v = make_float4(0.f, 0.f, 0.f, 0.f);
        if (grow < NN) v = *(const float4*)&x[(size_t)grow * F + col0];
        unsigned h01 = pack_bf16(v.x, v.y);
        unsigned h23 = pack_bf16(v.z, v.w);
        unsigned l01 = pack_bf16(v.x - bf16hi_f(v.x), v.y - bf16hi_f(v.y));
        unsigned l23 = pack_bf16(v.z - bf16hi_f(v.z), v.w - bf16hi_f(v.w));
        unsigned o = row * ROWB + col0 * 2;
        asm volatile("st.shared.v2.b32 [%0], {%1, %2};"
                     :: "r"(base + AH_OFF + o), "r"(h01), "r"(h23));
        asm volatile("st.shared.v2.b32 [%0], {%1, %2};"
                     :: "r"(base + AL_OFF + o), "r"(l01), "r"(l23));
    }
    if (tid < 128) { s_s1[tid] = 0.f; s_s2[tid] = 0.f; }
    __syncthreads();

    // ---- phase 2: mainloop ----
    float acc[2][8][4];
#pragma unroll
    for (int mi = 0; mi < 2; mi++)
#pragma unroll
        for (int ni = 0; ni < 8; ni++)
#pragma unroll
            for (int q = 0; q < 4; q++) acc[mi][ni][q] = 0.f;

    const int lrA = (lane & 7) + ((lane >> 3) & 1) * 8;
    const int kbA = (lane >> 4) * 16;
    const int lrB = (lane & 7) + (lane >> 4) * 8;
    const int kbB = ((lane >> 3) & 1) * 16;

    const unsigned aRowA = base + (warp_m * 32 + lrA) * ROWB + kbA;
    const unsigned aRowB = base + (warp_n * 64 + lrB) * ROWB + kbB;

    for (int k = 0; k < 8; k++) {
        const int kb = k * 32;
        unsigned ah[2][4], al[2][4], bh[4][4], bl[4][4];
#pragma unroll
        for (int mi = 0; mi < 2; mi++) {
            ldm4(ah[mi], aRowA + AH_OFF + mi * 16 * ROWB + kb);
            ldm4(al[mi], aRowA + AL_OFF + mi * 16 * ROWB + kb);
        }
#pragma unroll
        for (int j = 0; j < 4; j++) {
            ldm4(bh[j], aRowB + BH_OFF + j * 16 * ROWB + kb);
            ldm4(bl[j], aRowB + BL_OFF + j * 16 * ROWB + kb);
        }
#pragma unroll
        for (int mi = 0; mi < 2; mi++)
#pragma unroll
            for (int j = 0; j < 4; j++) {
                mma16816(acc[mi][2 * j],     ah[mi], bh[j][0], bh[j][1]);
                mma16816(acc[mi][2 * j + 1], ah[mi], bh[j][2], bh[j][3]);
                mma16816(acc[mi][2 * j],     ah[mi], bl[j][0], bl[j][1]);
                mma16816(acc[mi][2 * j + 1], ah[mi], bl[j][2], bl[j][3]);
                mma16816(acc[mi][2 * j],     al[mi], bh[j][0], bh[j][1]);
                mma16816(acc[mi][2 * j + 1], al[mi], bh[j][2], bh[j][3]);
            }
    }

    // ---- phase 3: epilogue — write h (fp32 + fp16 copy), fused s1/s2 ----
    float p1[2][2] = {{0.f, 0.f}, {0.f, 0.f}};
    float p2[2][2] = {{0.f, 0.f}, {0.f, 0.f}};
#pragma unroll
    for (int ni = 0; ni < 8; ni++) {
        int c = warp_n * 64 + ni * 8 + 2 * (lane & 3);
        float A1x = a[c], A1y = a[c + 1];
        float A2x = a[F + c], A2y = a[F + c + 1];
#pragma unroll
        for (int mi = 0; mi < 2; mi++) {
            float* f = acc[mi][ni];
            p1[mi][0] += f[0] * A1x + f[1] * A1y;
            p2[mi][0] += f[0] * A2x + f[1] * A2y;
            p1[mi][1] += f[2] * A1x + f[3] * A1y;
            p2[mi][1] += f[2] * A2x + f[3] * A2y;
            int row0 = rowBase + warp_m * 32 + mi * 16 + (lane >> 2);
            if (row0 < NN) {
                *(float2*)&g_h[(size_t)row0 * F + c] = make_float2(f[0], f[1]);
                *(__half2*)&g_hh[(size_t)row0 * F + c] = __floats2half2_rn(f[0], f[1]);
            }
            if (row0 + 8 < NN) {
                *(float2*)&g_h[(size_t)(row0 + 8) * F + c] = make_float2(f[2], f[3]);
                *(__half2*)&g_hh[(size_t)(row0 + 8) * F + c] = __floats2half2_rn(f[2], f[3]);
            }
        }
    }
#pragma unroll
    for (int mi = 0; mi < 2; mi++)
#pragma unroll
        for (int hf = 0; hf < 2; hf++) {
            float v1 = p1[mi][hf], v2 = p2[mi][hf];
            v1 += __shfl_xor_sync(0xffffffffu, v1, 1);
            v1 += __shfl_xor_sync(0xffffffffu, v1, 2);
            v2 += __shfl_xor_sync(0xffffffffu, v2, 1);
            v2 += __shfl_xor_sync(0xffffffffu, v2, 2);
            if ((lane & 3) == 0) {
                int lr = warp_m * 32 + mi * 16 + hf * 8 + (lane >> 2);
                atomicAdd(&s_s1[lr], v1);
                atomicAdd(&s_s2[lr], v2);
            }
        }
    __syncthreads();
    if (tid < 128) {
        int row = rowBase + tid;
        if (row < NN) { g_s1[row] = s_s1[tid]; g_s2[row] = s_s2[tid]; }
    }

    // ---- phase 4: histogram tail (independent work) ----
    for (int e = blockIdx.x * 256 + tid; e < EE; e += GB * 256)
        g_rank[e] = atomicAdd(&g_count[src[e]], 1);
}

// ---------------- single-kernel exclusive scan (decoupled aggregates)
__global__ void k_scan() {
    __shared__ int warpsums[32];
    __shared__ int s_prev;
    const int b = blockIdx.x;
    const int i = b * 1024 + threadIdx.x;
    const int lane = threadIdx.x & 31, w = threadIdx.x >> 5;

    int v = (i < NN) ? g_count[i] : 0;
    int sc = v;
#pragma unroll
    for (int off = 1; off < 32; off <<= 1) {
        int n = __shfl_up_sync(0xffffffffu, sc, off);
        if (lane >= off) sc += n;
    }
    if (lane == 31) warpsums[w] = sc;
    if (threadIdx.x == 0) s_prev = 0;
    __syncthreads();
    if (w == 0) {
        int ws = warpsums[lane];
#pragma unroll
        for (int off = 1; off < 32; off <<= 1) {
            int n = __shfl_up_sync(0xffffffffu, ws, off);
            if (lane >= off) ws += n;
        }
        warpsums[lane] = ws;
    }
    __syncthreads();

    if (threadIdx.x == 0) atomicExch(&g_agg[b], warpsums[31]);
    if (threadIdx.x < b) {
        volatile int* p = &g_agg[threadIdx.x];
        int ag;
        do { ag = *p; } while (ag < 0);
        atomicAdd(&s_prev, ag);
    }
    __syncthreads();

    int basew = (w > 0) ? warpsums[w - 1] : 0;
    if (i < NN) g_rowstart[i] = (sc + basew - v) + s_prev;
}

// -------- permute: 10 independent edges/thread (deep MLP), atomic-free
__global__ void k_permute(const int* __restrict__ src, const int* __restrict__ dst) {
    const int t = blockIdx.x * blockDim.x + threadIdx.x;
#pragma unroll
    for (int i = 0; i < EE / PT; i++) {
        int e = t + i * PT;
        int s = src[e];
        int d = dst[e];
        float scv = g_s1[s] + g_s2[d];
        float lr = fmaxf(scv, 0.2f * scv);        // leaky_relu
        float ev = expf(-lr);
        int pos = g_rowstart[s] + g_rank[e];
        g_pair[pos] = make_int2(d, __float_as_int(ev));
    }
}

// ------------------------------------------- gather + finalize (fused)
// One warp per node; broadcast pair loads (r9 style), fp16 h rows (half bytes).
__global__ void k_gather(float* __restrict__ out) {
    int node = blockIdx.x * 8 + (threadIdx.x >> 5);
    if (node >= NN) return;
    int lane = threadIdx.x & 31;
    int start = g_rowstart[node];
    int len = g_count[node];

    float4 acc = make_float4(0.f, 0.f, 0.f, 0.f);
    float rowsum = 0.0f;
    const size_t loff = (size_t)lane * 4;

    int j = 0;
    for (; j + 1 < len; j += 2) {
        int2 p0 = g_pair[start + j];          // broadcast LDG.64
        int2 p1 = g_pair[start + j + 1];
        float ev0 = __int_as_float(p0.y);
        float ev1 = __int_as_float(p1.y);
        uint2 q0 = *(const uint2*)(g_hh + (size_t)p0.x * F + loff);
        uint2 q1 = *(const uint2*)(g_hh + (size_t)p1.x * F + loff);
        float2 f00 = __half22float2(*(__half2*)&q0.x);
        float2 f01 = __half22float2(*(__half2*)&q0.y);
        float2 f10 = __half22float2(*(__half2*)&q1.x);
        float2 f11 = __half22float2(*(__half2*)&q1.y);
        rowsum += ev0 + ev1;
        acc.x += ev0 * f00.x + ev1 * f10.x;
        acc.y += ev0 * f00.y + ev1 * f10.y;
        acc.z += ev0 * f01.x + ev1 * f11.x;
        acc.w += ev0 * f01.y + ev1 * f11.y;
    }
    if (j < len) {
        int2 p0 = g_pair[start + j];
        float ev0 = __int_as_float(p0.y);
        uint2 q0 = *(const uint2*)(g_hh + (size_t)p0.x * F + loff);
        float2 f00 = __half22float2(*(__half2*)&q0.x);
        float2 f01 = __half22float2(*(__half2*)&q0.y);
        rowsum += ev0;
        acc.x += ev0 * f00.x; acc.y += ev0 * f00.y;
        acc.z += ev0 * f01.x; acc.w += ev0 * f01.y;
    }

    float inv = 1.0f / (rowsum + 1e-16f);
    float4 h4 = *(const float4*)(g_h + (size_t)node * F + loff);
    float4 r;
    float v;
    v = h4.x - acc.x * inv; r.x = (v > 0.f) ? v : expm1f(v);
    v = h4.y - acc.y * inv; r.y = (v > 0.f) ? v : expm1f(v);
    v = h4.z - acc.z * inv; r.z = (v > 0.f) ? v : expm1f(v);
    v = h4.w - acc.w * inv; r.w = (v > 0.f) ? v : expm1f(v);
    *(float4*)(out + (size_t)node * F + loff) = r;
}

// ---------------------------------------------------------------- launch
extern "C" void kernel_launch(void* const* d_in, const int* in_sizes, int n_in,
                              void* d_out, int out_size) {
    const float* x = (const float*)d_in[0];
    const float* W = (const float*)d_in[1];
    const float* a = (const float*)d_in[2];
    const int*   ei = (const int*)d_in[3];
    const int* src = ei;
    const int* dst = ei + EE;
    float* out = (float*)d_out;

    cudaFuncSetAttribute(k_gemm, cudaFuncAttributeMaxDynamicSharedMemorySize,
                         SMEM_BYTES);

    k_prep   <<<(NN + 255) / 256, 256>>>(W);
    k_gemm   <<<GB, 256, SMEM_BYTES>>>(x, a, src);
    k_scan   <<<NB, 1024>>>();
    k_permute<<<PT / 256, 256>>>(src, dst);
    k_gather <<<(NN + 7) / 8, 256>>>(out);
}

// round 15
// speedup vs baseline: 1.2139x; 1.0682x over previous
#include <cuda_runtime.h>
#include <cuda_bf16.h>
#include <math.h>

#define NN 50000
#define EE 640000
#define F  128
#define NB ((NN + 1023) / 1024)          // 49 scan blocks
#define GB ((NN + 127) / 128)            // 391 gemm blocks

// ---- smem layout (bytes). Rows padded to 272B (136 bf16) -> ldmatrix conflict-free
#define ROWB 272
#define AH_OFF 0
#define AL_OFF 34816
#define BH_OFF 69632
#define BL_OFF 104448
#define S1_OFF 139264
#define S2_OFF 139776
#define SMEM_BYTES 140288

// Scratch (static device globals: no allocation anywhere)
__device__ float    g_h[NN * F];       // fp32 h (own-row read in finalize)
__device__ unsigned g_hb[NN * 64];     // bf16 h pairs (gather reads)
__device__ float    g_s1[NN];
__device__ float    g_s2[NN];
__device__ int      g_count[NN];
__device__ int      g_rank[EE];
__device__ int      g_agg[64];
__device__ int2     g_sr[NN];          // (bitcast s1, rowstart)  — permute
__device__ int2     g_rc[NN];          // (rowstart, count)       — gather
__device__ int2     g_pair[EE];        // (dst, bitcast(e)) sorted by src
__device__ unsigned g_Bimg[16384];     // [BH: 8192 u32][BL: 8192 u32]

// ------------------------------------------------ PTX helpers (baseline ISA only)
__device__ __forceinline__ unsigned smem_u32(const void* p) {
    unsigned a;
    asm("{ .reg .u64 t; cvta.to.shared.u64 t, %1; cvt.u32.u64 %0, t; }"
        : "=r"(a) : "l"(p));
    return a;
}
__device__ __forceinline__ void ldm4(unsigned r[4], unsigned addr) {
    asm volatile("ldmatrix.sync.aligned.m8n8.x4.shared.b16 {%0,%1,%2,%3}, [%4];"
                 : "=r"(r[0]), "=r"(r[1]), "=r"(r[2]), "=r"(r[3]) : "r"(addr));
}
__device__ __forceinline__ void mma16816(float c[4], const unsigned a[4],
                                         unsigned b0, unsigned b1) {
    asm volatile("mma.sync.aligned.m16n8k16.row.col.f32.bf16.bf16.f32 "
                 "{%0,%1,%2,%3}, {%4,%5,%6,%7}, {%8,%9}, {%0,%1,%2,%3};"
                 : "+f"(c[0]), "+f"(c[1]), "+f"(c[2]), "+f"(c[3])
                 : "r"(a[0]), "r"(a[1]), "r"(a[2]), "r"(a[3]), "r"(b0), "r"(b1));
}
__device__ __forceinline__ unsigned pack_bf16(float x, float y) {
    unsigned short hx = __bfloat16_as_ushort(__float2bfloat16(x));
    unsigned short hy = __bfloat16_as_ushort(__float2bfloat16(y));
    return (unsigned)hx | ((unsigned)hy << 16);
}
__device__ __forceinline__ float bf16hi_f(float x) {   // value of bf16(x)
    unsigned short h = __bfloat16_as_ushort(__float2bfloat16(x));
    return __uint_as_float(((unsigned)h) << 16);
}
__device__ __forceinline__ unsigned cvt_bf16x2(float hi, float lo) {
    unsigned r;
    asm("cvt.rn.bf16x2.f32 %0, %1, %2;" : "=r"(r) : "f"(hi), "f"(lo));
    return r;
}
// bf16-pair unpack: exact, pure ALU
__device__ __forceinline__ float blo(unsigned u) { return __uint_as_float(u << 16); }
__device__ __forceinline__ float bhi(unsigned u) { return __uint_as_float(u & 0xFFFF0000u); }

// -------------------- prep: init counters + W -> bf16 hi/lo images [n][k]
__global__ void k_prep(const float* __restrict__ W) {
    int t = blockIdx.x * blockDim.x + threadIdx.x;
    if (t < NN) g_count[t] = 0;
    if (t < 64) g_agg[t] = -1;
    if (t < 8192) {
        int n = t >> 6, q = t & 63, k = 2 * q;
        float v0 = W[(size_t)k * F + n];          // B[n][k] = W[k][n]
        float v1 = W[(size_t)(k + 1) * F + n];
        float h0 = bf16hi_f(v0), h1 = bf16hi_f(v1);
        g_Bimg[n * 64 + q]        = pack_bf16(v0, v1);
        g_Bimg[8192 + n * 64 + q] = pack_bf16(v0 - h0, v1 - h1);
    }
}

// ------------- GEMM via mma.sync bf16-split + s1/s2 epilogue + hist tail
__global__ void __launch_bounds__(256, 1)
k_gemm(const float* __restrict__ x, const float* __restrict__ a,
       const int* __restrict__ src) {
    extern __shared__ char dsm[];
    const unsigned base = smem_u32(dsm);
    float* s_s1 = (float*)(dsm + S1_OFF);
    float* s_s2 = (float*)(dsm + S2_OFF);

    const int tid = threadIdx.x;
    const int lane = tid & 31;
    const int wid = tid >> 5;
    const int warp_m = wid >> 1;
    const int warp_n = wid & 1;
    const int rowBase = blockIdx.x * 128;

    // ---- phase 1: fill smem ----
    const float4* bimg4 = (const float4*)g_Bimg;
#pragma unroll
    for (int p = 0; p < 16; p++) {
        int i = p * 256 + tid;
        int half_ = i >> 11, j = i & 2047;
        int n = j >> 4, f4 = j & 15;
        *(float4*)(dsm + (half_ ? BL_OFF : BH_OFF) + n * ROWB + f4 * 16) = bimg4[i];
    }
#pragma unroll
    for (int p = 0; p < 16; p++) {
        int idx = p * 256 + tid;
        int row = idx >> 5;
        int col0 = (idx & 31) * 4;
        int grow = rowBase + row;
        float4 v = make_float4(0.f, 0.f, 0.f, 0.f);
        if (grow < NN) v = *(const float4*)&x[(size_t)grow * F + col0];
        unsigned h01 = pack_bf16(v.x, v.y);
        unsigned h23 = pack_bf16(v.z, v.w);
        unsigned l01 = pack_bf16(v.x - bf16hi_f(v.x), v.y - bf16hi_f(v.y));
        unsigned l23 = pack_bf16(v.z - bf16hi_f(v.z), v.w - bf16hi_f(v.w));
        unsigned o = row * ROWB + col0 * 2;
        asm volatile("st.shared.v2.b32 [%0], {%1, %2};"
                     :: "r"(base + AH_OFF + o), "r"(h01), "r"(h23));
        asm volatile("st.shared.v2.b32 [%0], {%1, %2};"
                     :: "r"(base + AL_OFF + o), "r"(l01), "r"(l23));
    }
    if (tid < 128) { s_s1[tid] = 0.f; s_s2[tid] = 0.f; }
    __syncthreads();

    // ---- phase 2: mainloop ----
    float acc[2][8][4];
#pragma unroll
    for (int mi = 0; mi < 2; mi++)
#pragma unroll
        for (int ni = 0; ni < 8; ni++)
#pragma unroll
            for (int q = 0; q < 4; q++) acc[mi][ni][q] = 0.f;

    const int lrA = (lane & 7) + ((lane >> 3) & 1) * 8;
    const int kbA = (lane >> 4) * 16;
    const int lrB = (lane & 7) + (lane >> 4) * 8;
    const int kbB = ((lane >> 3) & 1) * 16;

    const unsigned aRowA = base + (warp_m * 32 + lrA) * ROWB + kbA;
    const unsigned aRowB = base + (warp_n * 64 + lrB) * ROWB + kbB;

    for (int k = 0; k < 8; k++) {
        const int kb = k * 32;
        unsigned ah[2][4], al[2][4], bh[4][4], bl[4][4];
#pragma unroll
        for (int mi = 0; mi < 2; mi++) {
            ldm4(ah[mi], aRowA + AH_OFF + mi * 16 * ROWB + kb);
            ldm4(al[mi], aRowA + AL_OFF + mi * 16 * ROWB + kb);
        }
#pragma unroll
        for (int j = 0; j < 4; j++) {
            ldm4(bh[j], aRowB + BH_OFF + j * 16 * ROWB + kb);
            ldm4(bl[j], aRowB + BL_OFF + j * 16 * ROWB + kb);
        }
#pragma unroll
        for (int mi = 0; mi < 2; mi++)
#pragma unroll
            for (int j = 0; j < 4; j++) {
                mma16816(acc[mi][2 * j],     ah[mi], bh[j][0], bh[j][1]);
                mma16816(acc[mi][2 * j + 1], ah[mi], bh[j][2], bh[j][3]);
                mma16816(acc[mi][2 * j],     ah[mi], bl[j][0], bl[j][1]);
                mma16816(acc[mi][2 * j + 1], ah[mi], bl[j][2], bl[j][3]);
                mma16816(acc[mi][2 * j],     al[mi], bh[j][0], bh[j][1]);
                mma16816(acc[mi][2 * j + 1], al[mi], bh[j][2], bh[j][3]);
            }
    }

    // ---- phase 3: epilogue — write h (fp32 + bf16 copy), fused s1/s2 ----
    float p1[2][2] = {{0.f, 0.f}, {0.f, 0.f}};
    float p2[2][2] = {{0.f, 0.f}, {0.f, 0.f}};
#pragma unroll
    for (int ni = 0; ni < 8; ni++) {
        int c = warp_n * 64 + ni * 8 + 2 * (lane & 3);
        float A1x = a[c], A1y = a[c + 1];
        float A2x = a[F + c], A2y = a[F + c + 1];
#pragma unroll
        for (int mi = 0; mi < 2; mi++) {
            float* f = acc[mi][ni];
            p1[mi][0] += f[0] * A1x + f[1] * A1y;
            p2[mi][0] += f[0] * A2x + f[1] * A2y;
            p1[mi][1] += f[2] * A1x + f[3] * A1y;
            p2[mi][1] += f[2] * A2x + f[3] * A2y;
            int row0 = rowBase + warp_m * 32 + mi * 16 + (lane >> 2);
            if (row0 < NN) {
                *(float2*)&g_h[(size_t)row0 * F + c] = make_float2(f[0], f[1]);
                g_hb[(size_t)row0 * 64 + (c >> 1)] = cvt_bf16x2(f[1], f[0]);
            }
            if (row0 + 8 < NN) {
                *(float2*)&g_h[(size_t)(row0 + 8) * F + c] = make_float2(f[2], f[3]);
                g_hb[(size_t)(row0 + 8) * 64 + (c >> 1)] = cvt_bf16x2(f[3], f[2]);
            }
        }
    }
#pragma unroll
    for (int mi = 0; mi < 2; mi++)
#pragma unroll
        for (int hf = 0; hf < 2; hf++) {
            float v1 = p1[mi][hf], v2 = p2[mi][hf];
            v1 += __shfl_xor_sync(0xffffffffu, v1, 1);
            v1 += __shfl_xor_sync(0xffffffffu, v1, 2);
            v2 += __shfl_xor_sync(0xffffffffu, v2, 1);
            v2 += __shfl_xor_sync(0xffffffffu, v2, 2);
            if ((lane & 3) == 0) {
                int lr = warp_m * 32 + mi * 16 + hf * 8 + (lane >> 2);
                atomicAdd(&s_s1[lr], v1);
                atomicAdd(&s_s2[lr], v2);
            }
        }
    __syncthreads();
    if (tid < 128) {
        int row = rowBase + tid;
        if (row < NN) { g_s1[row] = s_s1[tid]; g_s2[row] = s_s2[tid]; }
    }

    // ---- phase 4: histogram tail (independent work) ----
    for (int e = blockIdx.x * 256 + tid; e < EE; e += GB * 256)
        g_rank[e] = atomicAdd(&g_count[src[e]], 1);
}

// -------- single-kernel exclusive scan; emits packed (s1,rowstart)+(rowstart,count)
__global__ void k_scan() {
    __shared__ int warpsums[32];
    __shared__ int s_prev;
    const int b = blockIdx.x;
    const int i = b * 1024 + threadIdx.x;
    const int lane = threadIdx.x & 31, w = threadIdx.x >> 5;

    int v = (i < NN) ? g_count[i] : 0;
    int sc = v;
#pragma unroll
    for (int off = 1; off < 32; off <<= 1) {
        int n = __shfl_up_sync(0xffffffffu, sc, off);
        if (lane >= off) sc += n;
    }
    if (lane == 31) warpsums[w] = sc;
    if (threadIdx.x == 0) s_prev = 0;
    __syncthreads();
    if (w == 0) {
        int ws = warpsums[lane];
#pragma unroll
        for (int off = 1; off < 32; off <<= 1) {
            int n = __shfl_up_sync(0xffffffffu, ws, off);
            if (lane >= off) ws += n;
        }
        warpsums[lane] = ws;
    }
    __syncthreads();

    if (threadIdx.x == 0) atomicExch(&g_agg[b], warpsums[31]);
    if (threadIdx.x < b) {
        volatile int* p = &g_agg[threadIdx.x];
        int ag;
        do { ag = *p; } while (ag < 0);
        atomicAdd(&s_prev, ag);
    }
    __syncthreads();

    int basew = (w > 0) ? warpsums[w - 1] : 0;
    if (i < NN) {
        int rs = (sc + basew - v) + s_prev;
        g_sr[i] = make_int2(__float_as_int(g_s1[i]), rs);
        g_rc[i] = make_int2(rs, v);
    }
}

// -------- permute: one random 8B load (s1+rowstart packed), atomic-free
__global__ void k_permute(const int* __restrict__ src, const int* __restrict__ dst) {
    int e = blockIdx.x * blockDim.x + threadIdx.x;
    if (e >= EE) return;
    int s = src[e], d = dst[e];
    int2 sr = g_sr[s];
    float scv = __int_as_float(sr.x) + g_s2[d];
    float lr = fmaxf(scv, 0.2f * scv);            // leaky_relu
    float ev = expf(-lr);
    g_pair[sr.y + g_rank[e]] = make_int2(d, __float_as_int(ev));
}

// ------------------------------------------- gather + finalize (fused)
// One warp per node; broadcast pair loads, bf16 rows (half bytes, ALU unpack).
__global__ void k_gather(float* __restrict__ out) {
    int node = blockIdx.x * 8 + (threadIdx.x >> 5);
    if (node >= NN) return;
    int lane = threadIdx.x & 31;
    int2 rc = g_rc[node];
    int start = rc.x;
    int len = rc.y;

    float4 acc = make_float4(0.f, 0.f, 0.f, 0.f);
    float rowsum = 0.0f;
    const size_t boff = (size_t)lane * 2;          // u32-pair offset in row

    int j = 0;
    for (; j + 1 < len; j += 2) {
        int2 p0 = g_pair[start + j];               // broadcast LDG.64
        int2 p1 = g_pair[start + j + 1];
        float ev0 = __int_as_float(p0.y);
        float ev1 = __int_as_float(p1.y);
        uint2 q0 = *(const uint2*)(g_hb + (size_t)p0.x * 64 + boff);
        uint2 q1 = *(const uint2*)(g_hb + (size_t)p1.x * 64 + boff);
        rowsum += ev0 + ev1;
        acc.x += ev0 * blo(q0.x) + ev1 * blo(q1.x);
        acc.y += ev0 * bhi(q0.x) + ev1 * bhi(q1.x);
        acc.z += ev0 * blo(q0.y) + ev1 * blo(q1.y);
        acc.w += ev0 * bhi(q0.y) + ev1 * bhi(q1.y);
    }
    if (j < len) {
        int2 p0 = g_pair[start + j];
        float ev0 = __int_as_float(p0.y);
        uint2 q0 = *(const uint2*)(g_hb + (size_t)p0.x * 64 + boff);
        rowsum += ev0;
        acc.x += ev0 * blo(q0.x); acc.y += ev0 * bhi(q0.x);
        acc.z += ev0 * blo(q0.y); acc.w += ev0 * bhi(q0.y);
    }

    float inv = 1.0f / (rowsum + 1e-16f);
    float4 h4 = *(const float4*)(g_h + (size_t)node * F + (size_t)lane * 4);
    float4 r;
    float v;
    v = h4.x - acc.x * inv; r.x = (v > 0.f) ? v : expm1f(v);
    v = h4.y - acc.y * inv; r.y = (v > 0.f) ? v : expm1f(v);
    v = h4.z - acc.z * inv; r.z = (v > 0.f) ? v : expm1f(v);
    v = h4.w - acc.w * inv; r.w = (v > 0.f) ? v : expm1f(v);
    *(float4*)(out + (size_t)node * F + (size_t)lane * 4) = r;
}

// ---------------------------------------------------------------- launch
extern "C" void kernel_launch(void* const* d_in, const int* in_sizes, int n_in,
                              void* d_out, int out_size) {
    const float* x = (const float*)d_in[0];
    const float* W = (const float*)d_in[1];
    const float* a = (const float*)d_in[2];
    const int*   ei = (const int*)d_in[3];
    const int* src = ei;
    const int* dst = ei + EE;
    float* out = (float*)d_out;

    cudaFuncSetAttribute(k_gemm, cudaFuncAttributeMaxDynamicSharedMemorySize,
                         SMEM_BYTES);

    k_prep   <<<(NN + 255) / 256, 256>>>(W);
    k_gemm   <<<GB, 256, SMEM_BYTES>>>(x, a, src);
    k_scan   <<<NB, 1024>>>();
    k_permute<<<(EE + 255) / 256, 256>>>(src, dst);
    k_gather <<<(NN + 7) / 8, 256>>>(out);
}